// round 14
// baseline (speedup 1.0000x reference)
#include <cuda_runtime.h>
#include <cuda_fp16.h>
#include <cstdint>

// ---------------------------------------------------------------------------
// QuantizedLinear: y[t,o] = scale[o] * sum_k x[t,k]*qW[o,k] + bias[o]
// TOKENS=256, IN_F=4096, OUT_F=14336. qW int32 in [0,127) -> exact in fp16.
// R14: 128x128 tile, fp16 m16n8k16, 2 CTAs/SM. W path bypasses int SMEM
// staging: LDG.128 -> register magic-convert -> STS.64 fp16 (pipelined one
// stage ahead). Cuts SMEM traffic/stage 96KB -> 64KB (the measured binder).
// ---------------------------------------------------------------------------

#define TOKENS 256
#define IN_F   4096
#define OUT_F  14336

#define M_TILE 128
#define N_TILE 128
#define KC     32                 // K elems per stage
#define NST    (IN_F / KC)        // 128 stages
#define NTHREADS 256

// fp16 tile rows: 32 halfs = 64B data + 16B pad = 80B. Bank stride 20 ->
// every ldmatrix 8-row x 16B phase covers all 32 banks once (conflict-free).
#define ROWB      80
#define A_STAGE_B (M_TILE * ROWB)     // 10240 (4 slots)
#define BF_BUF_B  (N_TILE * ROWB)     // 10240 (2 parity buffers)

#define SM_SCALE 0
#define SM_BIAS  512
#define SM_A0    1024
#define SM_BF0   (SM_A0 + 4 * A_STAGE_B)     // 41984
#define SM_TOTAL (SM_BF0 + 2 * BF_BUF_B)     // 62464 (x2 CTAs = 124928)

__device__ __half g_x_f16[TOKENS * IN_F];

// ---------------------------------------------------------------------------
__device__ __forceinline__ uint32_t smem_u32(const void* p) {
    uint32_t a;
    asm("{ .reg .u64 t; cvta.to.shared.u64 t, %1; cvt.u32.u64 %0, t; }"
        : "=r"(a) : "l"(p));
    return a;
}

#define CP_ASYNC16(dst, src) \
    asm volatile("cp.async.cg.shared.global [%0], [%1], 16;" :: "r"(dst), "l"(src))
#define CP_COMMIT() asm volatile("cp.async.commit_group;" ::: "memory")
#define CP_WAIT(n)  asm volatile("cp.async.wait_group %0;" :: "n"(n) : "memory")

#define LDMX4(r0, r1, r2, r3, addr) \
    asm volatile("ldmatrix.sync.aligned.m8n8.x4.shared.b16 {%0,%1,%2,%3}, [%4];" \
                 : "=r"(r0), "=r"(r1), "=r"(r2), "=r"(r3) : "r"(addr))

__device__ __forceinline__ void mma_f16(float* c, const uint32_t* a, const uint32_t* b) {
    asm volatile(
        "mma.sync.aligned.m16n8k16.row.col.f32.f16.f16.f32 "
        "{%0,%1,%2,%3}, {%4,%5,%6,%7}, {%8,%9}, {%0,%1,%2,%3};"
        : "+f"(c[0]), "+f"(c[1]), "+f"(c[2]), "+f"(c[3])
        : "r"(a[0]), "r"(a[1]), "r"(a[2]), "r"(a[3]), "r"(b[0]), "r"(b[1]));
}

// Exact int(0..126) pair -> fp16x2: gather low bytes, OR 0x6400 (=1024.0 bits,
// ULP=1 in [1024,2048)), subtract 1024. 3 ops per 2 elements.
__device__ __forceinline__ uint32_t int2_to_h2(uint32_t lo, uint32_t hi) {
    uint32_t p;
    asm("prmt.b32 %0, %1, %2, 0x5410;" : "=r"(p) : "r"(lo), "r"(hi));
    p = (p & 0x00FF00FFu) | 0x64006400u;
    uint32_t r;
    asm("sub.rn.f16x2 %0, %1, %2;" : "=r"(r) : "r"(p), "r"(0x64006400u));
    return r;
}

// ---------------------------------------------------------------------------
__global__ void __launch_bounds__(256) prep_x_kernel(const float* __restrict__ x) {
    int i = blockIdx.x * blockDim.x + threadIdx.x;   // float4 index
    const float4 v = reinterpret_cast<const float4*>(x)[i];
    __half2 h0 = __floats2half2_rn(v.x, v.y);
    __half2 h1 = __floats2half2_rn(v.z, v.w);
    uint2 p;
    p.x = *reinterpret_cast<uint32_t*>(&h0);
    p.y = *reinterpret_cast<uint32_t*>(&h1);
    reinterpret_cast<uint2*>(g_x_f16)[i] = p;
}

// ---------------------------------------------------------------------------
__global__ void __launch_bounds__(NTHREADS, 2) qlin_gemm_kernel(
    const int*   __restrict__ W,
    const float* __restrict__ scale,
    const float* __restrict__ bias,
    float*       __restrict__ out)
{
    extern __shared__ char smem[];
    const uint32_t sb = smem_u32(smem);
    const int tid = threadIdx.x;
    const int wid = tid >> 5;
    const int lid = tid & 31;
    const int g   = lid >> 2;
    const int t   = lid & 3;
    const int wm  = wid & 1;     // 2 M warp-rows (64 tokens)
    const int wn  = wid >> 1;    // 4 N warp-cols (32 feats)
    const int n0  = blockIdx.x * N_TILE;
    const int m0  = blockIdx.y * M_TILE;

    if (tid < N_TILE) {
        ((float*)(smem + SM_SCALE))[tid] = scale[n0 + tid];
        ((float*)(smem + SM_BIAS))[tid]  = bias[n0 + tid];
    }

    // ---- A cp.async chunk mapping (128 rows x 64B = 512 chunks, 2/thread) --
    uint32_t aSoff[2]; const __half* aG[2];
#pragma unroll
    for (int i = 0; i < 2; i++) {
        int c = tid + i * NTHREADS;
        int row = c >> 2, ca = c & 3;
        aSoff[i] = (uint32_t)(row * ROWB + ca * 16);
        aG[i]    = g_x_f16 + (size_t)(m0 + row) * IN_F + ca * 8;
    }
    // ---- W LDG mapping (128 rows x 128B int = 1024 x16B chunks, 4/thread) --
    uint32_t bFoff[4]; const int4* bG[4];
#pragma unroll
    for (int i = 0; i < 4; i++) {
        int c = tid + i * NTHREADS;         // 0..1023
        int row = c >> 3, cb = c & 7;
        bFoff[i] = (uint32_t)(row * ROWB + cb * 8);
        bG[i]    = reinterpret_cast<const int4*>(
                       W + (size_t)(n0 + row) * IN_F + cb * 4);
    }

    // ---- prologue ---------------------------------------------------------
    // A stages 0..2 in flight (3 groups committed)
#pragma unroll
    for (int s = 0; s < 3; s++) {
        const uint32_t ab = sb + SM_A0 + s * A_STAGE_B;
        const int kb = s * KC;
#pragma unroll
        for (int i = 0; i < 2; i++) CP_ASYNC16(ab + aSoff[i], aG[i] + kb);
        CP_COMMIT();
    }
    // W(0) -> regs -> convert -> Bf[0]; then W(1) -> regs
    int4 wreg[4];
#pragma unroll
    for (int i = 0; i < 4; i++) wreg[i] = bG[i][0];
    {
        char* bf = smem + SM_BF0;
#pragma unroll
        for (int i = 0; i < 4; i++) {
            uint2 p;
            p.x = int2_to_h2((uint32_t)wreg[i].x, (uint32_t)wreg[i].y);
            p.y = int2_to_h2((uint32_t)wreg[i].z, (uint32_t)wreg[i].w);
            *reinterpret_cast<uint2*>(bf + bFoff[i]) = p;
        }
    }
#pragma unroll
    for (int i = 0; i < 4; i++) wreg[i] = bG[i][KC / 4];   // stage 1
    CP_WAIT(2);          // A(0) arrived
    __syncthreads();     // publish Bf[0]

    float acc[4][4][4];
#pragma unroll
    for (int i = 0; i < 4; i++)
#pragma unroll
        for (int j = 0; j < 4; j++)
#pragma unroll
            for (int c = 0; c < 4; c++) acc[i][j][c] = 0.0f;

    // ---- per-thread ldmatrix bases ---------------------------------------
    // A x4 (16 rows x 16 k): lane groups -> (r+0,k0)/(r+8,k0)/(r+0,k8)/(r+8,k8)
    const uint32_t aLM = sb + SM_A0 +
        (uint32_t)((wm * 64 + (lid & 7) + 8 * ((lid >> 3) & 1)) * ROWB
                   + (lid >> 4) * 16);
    // B x4 (16 n-rows x 16 k): groups -> (n+0,k0)/(n+0,k8)/(n+8,k0)/(n+8,k8)
    const uint32_t bLM = sb + SM_BF0 +
        (uint32_t)((wn * 32 + (lid & 7) + 8 * (lid >> 4)) * ROWB
                   + ((lid >> 3) & 1) * 16);

    // ---- main loop --------------------------------------------------------
    // Invariant at top of iter s: Bf[s&1] = stage s (published), wreg = stage
    // s+1, A slot s&3 = stage s arrived, A committed <= s+2.
#pragma unroll 1
    for (int s = 0; s < NST; s++) {
        // A(s+3) -> slot (s+3)&3 (freed by compute(s-1), ordered by barrier)
        if (s + 3 < NST) {
            const uint32_t ab = sb + SM_A0 + ((s + 3) & 3) * A_STAGE_B;
            const int kb = (s + 3) * KC;
#pragma unroll
            for (int i = 0; i < 2; i++) CP_ASYNC16(ab + aSoff[i], aG[i] + kb);
            CP_COMMIT();
        }
        CP_WAIT(2);     // A(s+1) arrived (only A groups in flight)

        // convert wreg (stage s+1) -> Bf[(s+1)&1]. Same-parity reader was
        // compute(s-1), retired before barrier(s-1).
        if (s + 1 < NST) {
            char* bf = smem + SM_BF0 + ((s + 1) & 1) * BF_BUF_B;
#pragma unroll
            for (int i = 0; i < 4; i++) {
                uint2 p;
                p.x = int2_to_h2((uint32_t)wreg[i].x, (uint32_t)wreg[i].y);
                p.y = int2_to_h2((uint32_t)wreg[i].z, (uint32_t)wreg[i].w);
                *reinterpret_cast<uint2*>(bf + bFoff[i]) = p;
            }
        }
        // W(s+2) -> regs (latency absorbed by compute(s) + barrier)
        if (s + 2 < NST) {
            const int kb4 = (s + 2) * (KC / 4);
#pragma unroll
            for (int i = 0; i < 4; i++) wreg[i] = bG[i][kb4];
        }

        // compute stage s: two k16 steps, fragments via ldmatrix.x4
        const uint32_t aS = aLM + (s & 3) * A_STAGE_B;
        const uint32_t bS = bLM + (s & 1) * BF_BUF_B;
#pragma unroll
        for (int kk = 0; kk < 2; kk++) {
            const uint32_t ko = (uint32_t)(kk * 32);
            uint32_t a[4][4], b[4][2];
#pragma unroll
            for (int i = 0; i < 4; i++)
                LDMX4(a[i][0], a[i][1], a[i][2], a[i][3],
                      aS + (uint32_t)(i * 16 * ROWB) + ko);
#pragma unroll
            for (int jp = 0; jp < 2; jp++)
                LDMX4(b[2 * jp][0], b[2 * jp][1], b[2 * jp + 1][0], b[2 * jp + 1][1],
                      bS + (uint32_t)(jp * 16 * ROWB) + ko);
#pragma unroll
            for (int i = 0; i < 4; i++)
#pragma unroll
                for (int j = 0; j < 4; j++)
                    mma_f16(acc[i][j], a[i], b[j]);
        }

        __syncthreads();   // publishes Bf[(s+1)&1] + guards A-slot reuse
    }

    // ---- epilogue ---------------------------------------------------------
    const float* s_sc = (const float*)(smem + SM_SCALE);
    const float* s_bi = (const float*)(smem + SM_BIAS);
#pragma unroll
    for (int i = 0; i < 4; i++) {
        const int m = m0 + wm * 64 + i * 16 + g;
#pragma unroll
        for (int j = 0; j < 4; j++) {
            const int nl = wn * 32 + j * 8 + 2 * t;
            const float sc0 = s_sc[nl],     bi0 = s_bi[nl];
            const float sc1 = s_sc[nl + 1], bi1 = s_bi[nl + 1];
            float2 v0 = { acc[i][j][0] * sc0 + bi0, acc[i][j][1] * sc1 + bi1 };
            float2 v1 = { acc[i][j][2] * sc0 + bi0, acc[i][j][3] * sc1 + bi1 };
            *reinterpret_cast<float2*>(out + (size_t)m * OUT_F + n0 + nl) = v0;
            *reinterpret_cast<float2*>(out + (size_t)(m + 8) * OUT_F + n0 + nl) = v1;
        }
    }
}

// ---------------------------------------------------------------------------
extern "C" void kernel_launch(void* const* d_in, const int* in_sizes, int n_in,
                              void* d_out, int out_size) {
    const float* x     = (const float*)d_in[0];
    const int*   W     = (const int*)  d_in[1];
    const float* scale = (const float*)d_in[2];
    const float* bias  = (const float*)d_in[3];
    float*       out   = (float*)d_out;

    (void)in_sizes; (void)n_in; (void)out_size;

    cudaFuncSetAttribute(qlin_gemm_kernel,
                         cudaFuncAttributeMaxDynamicSharedMemorySize, SM_TOTAL);

    prep_x_kernel<<<(TOKENS * IN_F / 4) / 256, 256>>>(x);   // float4 path

    dim3 grid(OUT_F / N_TILE, TOKENS / M_TILE);   // (112, 2) -> 2 CTAs/SM
    qlin_gemm_kernel<<<grid, NTHREADS, SM_TOTAL>>>(W, scale, bias, out);
}

// round 16
// speedup vs baseline: 1.0171x; 1.0171x over previous
#include <cuda_runtime.h>
#include <cuda_fp16.h>
#include <cstdint>

// ---------------------------------------------------------------------------
// QuantizedLinear: y[t,o] = scale[o] * sum_k x[t,k]*qW[o,k] + bias[o]
// TOKENS=256, IN_F=4096, OUT_F=14336. qW int32 in [0,127) -> exact in fp16.
// R15 (resubmit): R14 base (128x128 tile, fp16 m16n8k16, W: LDG->reg
// convert->STS, 2 CTAs/SM) + CO-RESIDENT CTA PHASE STAGGER (delay bid>=148
// by ~600 clocks so each SM's CTA pair runs ldm/mma bursts in antiphase)
// + eager kk0 ldmatrix hoisted to stage top (hides L1 latency under
// convert/prefetch issue).
// ---------------------------------------------------------------------------

#define TOKENS 256
#define IN_F   4096
#define OUT_F  14336

#define M_TILE 128
#define N_TILE 128
#define KC     32                 // K elems per stage
#define NST    (IN_F / KC)        // 128 stages
#define NTHREADS 256

// fp16 tile rows: 32 halfs = 64B data + 16B pad = 80B. Bank stride 20 ->
// every ldmatrix 8-row x 16B phase covers all 32 banks once (conflict-free).
#define ROWB      80
#define A_STAGE_B (M_TILE * ROWB)     // 10240 (4 slots)
#define BF_BUF_B  (N_TILE * ROWB)     // 10240 (2 parity buffers)

#define SM_SCALE 0
#define SM_BIAS  512
#define SM_A0    1024
#define SM_BF0   (SM_A0 + 4 * A_STAGE_B)     // 41984
#define SM_TOTAL (SM_BF0 + 2 * BF_BUF_B)     // 62464 (x2 CTAs = 124928)

__device__ __half g_x_f16[TOKENS * IN_F];

// ---------------------------------------------------------------------------
__device__ __forceinline__ uint32_t smem_u32(const void* p) {
    uint32_t a;
    asm("{ .reg .u64 t; cvta.to.shared.u64 t, %1; cvt.u32.u64 %0, t; }"
        : "=r"(a) : "l"(p));
    return a;
}

#define CP_ASYNC16(dst, src) \
    asm volatile("cp.async.cg.shared.global [%0], [%1], 16;" :: "r"(dst), "l"(src))
#define CP_COMMIT() asm volatile("cp.async.commit_group;" ::: "memory")
#define CP_WAIT(n)  asm volatile("cp.async.wait_group %0;" :: "n"(n) : "memory")

#define LDMX4(r0, r1, r2, r3, addr) \
    asm volatile("ldmatrix.sync.aligned.m8n8.x4.shared.b16 {%0,%1,%2,%3}, [%4];" \
                 : "=r"(r0), "=r"(r1), "=r"(r2), "=r"(r3) : "r"(addr))

__device__ __forceinline__ void mma_f16(float* c, const uint32_t* a, const uint32_t* b) {
    asm volatile(
        "mma.sync.aligned.m16n8k16.row.col.f32.f16.f16.f32 "
        "{%0,%1,%2,%3}, {%4,%5,%6,%7}, {%8,%9}, {%0,%1,%2,%3};"
        : "+f"(c[0]), "+f"(c[1]), "+f"(c[2]), "+f"(c[3])
        : "r"(a[0]), "r"(a[1]), "r"(a[2]), "r"(a[3]), "r"(b[0]), "r"(b[1]));
}

// Exact int(0..126) pair -> fp16x2: gather low bytes, OR 0x6400 (=1024.0 bits,
// ULP=1 in [1024,2048)), subtract 1024. 3 ops per 2 elements.
__device__ __forceinline__ uint32_t int2_to_h2(uint32_t lo, uint32_t hi) {
    uint32_t p;
    asm("prmt.b32 %0, %1, %2, 0x5410;" : "=r"(p) : "r"(lo), "r"(hi));
    p = (p & 0x00FF00FFu) | 0x64006400u;
    uint32_t r;
    asm("sub.rn.f16x2 %0, %1, %2;" : "=r"(r) : "r"(p), "r"(0x64006400u));
    return r;
}

// ---------------------------------------------------------------------------
__global__ void __launch_bounds__(256) prep_x_kernel(const float* __restrict__ x) {
    int i = blockIdx.x * blockDim.x + threadIdx.x;   // float4 index
    const float4 v = reinterpret_cast<const float4*>(x)[i];
    __half2 h0 = __floats2half2_rn(v.x, v.y);
    __half2 h1 = __floats2half2_rn(v.z, v.w);
    uint2 p;
    p.x = *reinterpret_cast<uint32_t*>(&h0);
    p.y = *reinterpret_cast<uint32_t*>(&h1);
    reinterpret_cast<uint2*>(g_x_f16)[i] = p;
}

// ---------------------------------------------------------------------------
__global__ void __launch_bounds__(NTHREADS, 2) qlin_gemm_kernel(
    const int*   __restrict__ W,
    const float* __restrict__ scale,
    const float* __restrict__ bias,
    float*       __restrict__ out)
{
    extern __shared__ char smem[];
    const uint32_t sb = smem_u32(smem);
    const int tid = threadIdx.x;
    const int wid = tid >> 5;
    const int lid = tid & 31;
    const int g   = lid >> 2;
    const int t   = lid & 3;
    const int wm  = wid & 1;     // 2 M warp-rows (64 tokens)
    const int wn  = wid >> 1;    // 4 N warp-cols (32 feats)
    const int n0  = blockIdx.x * N_TILE;
    const int m0  = blockIdx.y * M_TILE;

    // ---- phase stagger: co-resident pairs are (b, b+148) under classic
    // placement (smid = LUT[bid % 148]). Delay the second of each pair by
    // ~half a stage so the per-SM CTA pair runs ldm/mma bursts in antiphase.
    // Output-invariant (no arithmetic change); bounded spin, uniform branch.
    {
        const int bidlin = blockIdx.x + (int)gridDim.x * blockIdx.y;
        if (bidlin >= 148) {
            long long t0 = clock64();
            while (clock64() - t0 < 600) { }
        }
    }

    if (tid < N_TILE) {
        ((float*)(smem + SM_SCALE))[tid] = scale[n0 + tid];
        ((float*)(smem + SM_BIAS))[tid]  = bias[n0 + tid];
    }

    // ---- A cp.async chunk mapping (128 rows x 64B = 512 chunks, 2/thread) --
    uint32_t aSoff[2]; const __half* aG[2];
#pragma unroll
    for (int i = 0; i < 2; i++) {
        int c = tid + i * NTHREADS;
        int row = c >> 2, ca = c & 3;
        aSoff[i] = (uint32_t)(row * ROWB + ca * 16);
        aG[i]    = g_x_f16 + (size_t)(m0 + row) * IN_F + ca * 8;
    }
    // ---- W LDG mapping (128 rows x 128B int = 1024 x16B chunks, 4/thread) --
    uint32_t bFoff[4]; const int4* bG[4];
#pragma unroll
    for (int i = 0; i < 4; i++) {
        int c = tid + i * NTHREADS;         // 0..1023
        int row = c >> 3, cb = c & 7;
        bFoff[i] = (uint32_t)(row * ROWB + cb * 8);
        bG[i]    = reinterpret_cast<const int4*>(
                       W + (size_t)(n0 + row) * IN_F + cb * 4);
    }

    // ---- prologue ---------------------------------------------------------
#pragma unroll
    for (int s = 0; s < 3; s++) {
        const uint32_t ab = sb + SM_A0 + s * A_STAGE_B;
        const int kb = s * KC;
#pragma unroll
        for (int i = 0; i < 2; i++) CP_ASYNC16(ab + aSoff[i], aG[i] + kb);
        CP_COMMIT();
    }
    int4 wreg[4];
#pragma unroll
    for (int i = 0; i < 4; i++) wreg[i] = bG[i][0];
    {
        char* bf = smem + SM_BF0;
#pragma unroll
        for (int i = 0; i < 4; i++) {
            uint2 p;
            p.x = int2_to_h2((uint32_t)wreg[i].x, (uint32_t)wreg[i].y);
            p.y = int2_to_h2((uint32_t)wreg[i].z, (uint32_t)wreg[i].w);
            *reinterpret_cast<uint2*>(bf + bFoff[i]) = p;
        }
    }
#pragma unroll
    for (int i = 0; i < 4; i++) wreg[i] = bG[i][KC / 4];   // stage 1
    CP_WAIT(2);          // A(0) arrived
    __syncthreads();     // publish Bf[0]

    float acc[4][4][4];
#pragma unroll
    for (int i = 0; i < 4; i++)
#pragma unroll
        for (int j = 0; j < 4; j++)
#pragma unroll
            for (int c = 0; c < 4; c++) acc[i][j][c] = 0.0f;

    // ---- per-thread ldmatrix bases ---------------------------------------
    const uint32_t aLM = sb + SM_A0 +
        (uint32_t)((wm * 64 + (lid & 7) + 8 * ((lid >> 3) & 1)) * ROWB
                   + (lid >> 4) * 16);
    const uint32_t bLM = sb + SM_BF0 +
        (uint32_t)((wn * 32 + (lid & 7) + 8 * (lid >> 4)) * ROWB
                   + ((lid >> 3) & 1) * 16);

    // ---- main loop --------------------------------------------------------
    // Invariant at top of iter s: Bf[s&1] = stage s (published), wreg = stage
    // s+1, A slot s&3 = stage s arrived, A committed <= s+2.
#pragma unroll 1
    for (int s = 0; s < NST; s++) {
        const uint32_t aS = aLM + (s & 3) * A_STAGE_B;
        const uint32_t bS = bLM + (s & 1) * BF_BUF_B;

        // 1. EAGER kk0 fragments — L1 latency hides under steps 2-4.
        uint32_t a0[4][4], b0[4][2];
#pragma unroll
        for (int i = 0; i < 4; i++)
            LDMX4(a0[i][0], a0[i][1], a0[i][2], a0[i][3],
                  aS + (uint32_t)(i * 16 * ROWB));
#pragma unroll
        for (int jp = 0; jp < 2; jp++)
            LDMX4(b0[2 * jp][0], b0[2 * jp][1], b0[2 * jp + 1][0], b0[2 * jp + 1][1],
                  bS + (uint32_t)(jp * 16 * ROWB));

        // 2. prefetch A(s+3); ensure A(s+1) arrived
        if (s + 3 < NST) {
            const uint32_t ab = sb + SM_A0 + ((s + 3) & 3) * A_STAGE_B;
            const int kb = (s + 3) * KC;
#pragma unroll
            for (int i = 0; i < 2; i++) CP_ASYNC16(ab + aSoff[i], aG[i] + kb);
            CP_COMMIT();
        }
        CP_WAIT(2);

        // 3. convert wreg (stage s+1) -> Bf[(s+1)&1] (same-parity readers
        //    were stage s-1's ldms, retired before barrier(s-1)).
        if (s + 1 < NST) {
            char* bf = smem + SM_BF0 + ((s + 1) & 1) * BF_BUF_B;
#pragma unroll
            for (int i = 0; i < 4; i++) {
                uint2 p;
                p.x = int2_to_h2((uint32_t)wreg[i].x, (uint32_t)wreg[i].y);
                p.y = int2_to_h2((uint32_t)wreg[i].z, (uint32_t)wreg[i].w);
                *reinterpret_cast<uint2*>(bf + bFoff[i]) = p;
            }
        }
        // 4. W(s+2) -> regs (latency absorbed by compute + barrier)
        if (s + 2 < NST) {
            const int kb4 = (s + 2) * (KC / 4);
#pragma unroll
            for (int i = 0; i < 4; i++) wreg[i] = bG[i][kb4];
        }

        // 5. mma kk0
#pragma unroll
        for (int i = 0; i < 4; i++)
#pragma unroll
            for (int j = 0; j < 4; j++)
                mma_f16(acc[i][j], a0[i], b0[j]);

        // 6. kk1 fragments (issue overlaps mma kk0 execution)
        uint32_t a1[4][4], b1[4][2];
#pragma unroll
        for (int i = 0; i < 4; i++)
            LDMX4(a1[i][0], a1[i][1], a1[i][2], a1[i][3],
                  aS + (uint32_t)(i * 16 * ROWB) + 32);
#pragma unroll
        for (int jp = 0; jp < 2; jp++)
            LDMX4(b1[2 * jp][0], b1[2 * jp][1], b1[2 * jp + 1][0], b1[2 * jp + 1][1],
                  bS + (uint32_t)(jp * 16 * ROWB) + 32);

        // 7. mma kk1
#pragma unroll
        for (int i = 0; i < 4; i++)
#pragma unroll
            for (int j = 0; j < 4; j++)
                mma_f16(acc[i][j], a1[i], b1[j]);

        __syncthreads();   // publishes Bf[(s+1)&1] + guards A-slot reuse
    }

    // ---- epilogue ---------------------------------------------------------
    const float* s_sc = (const float*)(smem + SM_SCALE);
    const float* s_bi = (const float*)(smem + SM_BIAS);
#pragma unroll
    for (int i = 0; i < 4; i++) {
        const int m = m0 + wm * 64 + i * 16 + g;
#pragma unroll
        for (int j = 0; j < 4; j++) {
            const int nl = wn * 32 + j * 8 + 2 * t;
            const float sc0 = s_sc[nl],     bi0 = s_bi[nl];
            const float sc1 = s_sc[nl + 1], bi1 = s_bi[nl + 1];
            float2 v0 = { acc[i][j][0] * sc0 + bi0, acc[i][j][1] * sc1 + bi1 };
            float2 v1 = { acc[i][j][2] * sc0 + bi0, acc[i][j][3] * sc1 + bi1 };
            *reinterpret_cast<float2*>(out + (size_t)m * OUT_F + n0 + nl) = v0;
            *reinterpret_cast<float2*>(out + (size_t)(m + 8) * OUT_F + n0 + nl) = v1;
        }
    }
}

// ---------------------------------------------------------------------------
extern "C" void kernel_launch(void* const* d_in, const int* in_sizes, int n_in,
                              void* d_out, int out_size) {
    const float* x     = (const float*)d_in[0];
    const int*   W     = (const int*)  d_in[1];
    const float* scale = (const float*)d_in[2];
    const float* bias  = (const float*)d_in[3];
    float*       out   = (float*)d_out;

    (void)in_sizes; (void)n_in; (void)out_size;

    cudaFuncSetAttribute(qlin_gemm_kernel,
                         cudaFuncAttributeMaxDynamicSharedMemorySize, SM_TOTAL);

    prep_x_kernel<<<(TOKENS * IN_F / 4) / 256, 256>>>(x);

    dim3 grid(OUT_F / N_TILE, TOKENS / M_TILE);   // (112, 2) -> 2 CTAs/SM
    qlin_gemm_kernel<<<grid, NTHREADS, SM_TOTAL>>>(W, scale, bias, out);
}